// round 9
// baseline (speedup 1.0000x reference)
#include <cuda_runtime.h>
#include <math.h>

#define B 8
#define N 2048
#define F 128
#define BN (B*N)
#define G2 64          // chunks per batch (scan)
#define C2 32          // rows per chunk (G2*C2 == N)

// ---------------- scratch (device globals) ----------------
__device__ float g_Wh[BN * F];          // 8 MB
__device__ float g_s1[BN];
__device__ float g_s2[BN];
__device__ float g_s2s[BN];             // sorted s2 per batch (ascending)
__device__ int   g_perm[BN];
__device__ float g_S[BN * F];           // suffix sums of w_j * Wh[perm[j],:]
__device__ float g_Z[B * (N + 1)];      // scalar suffix sums of w
__device__ float g_mean[B * F];
__device__ float g_mx[B];               // per-batch max of s2
__device__ float g_pw[B][G2][F];        // chunk partial weighted sums
__device__ float g_pm[B][G2][F];        // chunk partial plain sums (for mean)
__device__ float g_pz[B][G2];           // chunk partial scalar w sums
__device__ int   g_flag[B * G2];        // chunk-done flags (zeroed by rank_kernel)

// ---- Kernel 1: Wh = h @ W^T. 128x128 tile, 8x8/thread, k-major smem ----
#define SST 132        // smem row stride
__global__ void __launch_bounds__(256, 1) gemm_kernel(const float* __restrict__ A,
                                                      const float* __restrict__ W,
                                                      const float* __restrict__ a) {
    __shared__ float AsT[16][SST];    // AsT[k][m]
    __shared__ float Bs[16][SST];     // Bs[k][n] = W[n][k]
    __shared__ float sa[256];
    const int m0 = blockIdx.x * 128;
    const int tid = threadIdx.x;
    sa[tid] = a[tid];

    const int ty = tid >> 4;          // 0..15 -> rows ty*8..+7
    const int tx = tid & 15;          // 0..15 -> cols tx*8..+7

    float acc[8][8];
#pragma unroll
    for (int i = 0; i < 8; i++)
#pragma unroll
        for (int j = 0; j < 8; j++) acc[i][j] = 0.f;

    for (int k0 = 0; k0 < 128; k0 += 16) {
#pragma unroll
        for (int s = 0; s < 2; s++) {
            int q = tid + s * 256;
            int m = q >> 2;
            int kq = (q & 3) * 4;
            float4 av = *(const float4*)(A + (size_t)(m0 + m) * 128 + k0 + kq);
            AsT[kq + 0][m] = av.x; AsT[kq + 1][m] = av.y;
            AsT[kq + 2][m] = av.z; AsT[kq + 3][m] = av.w;
            float4 wv = *(const float4*)(W + (size_t)m * 128 + k0 + kq);
            Bs[kq + 0][m] = wv.x; Bs[kq + 1][m] = wv.y;
            Bs[kq + 2][m] = wv.z; Bs[kq + 3][m] = wv.w;
        }
        __syncthreads();
#pragma unroll
        for (int kk = 0; kk < 16; kk++) {
            float af[8], bf[8];
            *(float4*)&af[0] = *(const float4*)&AsT[kk][ty * 8];
            *(float4*)&af[4] = *(const float4*)&AsT[kk][ty * 8 + 4];
            *(float4*)&bf[0] = *(const float4*)&Bs[kk][tx * 8];
            *(float4*)&bf[4] = *(const float4*)&Bs[kk][tx * 8 + 4];
#pragma unroll
            for (int i = 0; i < 8; i++)
#pragma unroll
                for (int j = 0; j < 8; j++) acc[i][j] = fmaf(af[i], bf[j], acc[i][j]);
        }
        __syncthreads();
    }
#pragma unroll
    for (int i = 0; i < 8; i++) {
        const int m = m0 + ty * 8 + i;
        float* crow = g_Wh + (size_t)m * 128 + tx * 8;
        *(float4*)(crow + 0) = make_float4(acc[i][0], acc[i][1], acc[i][2], acc[i][3]);
        *(float4*)(crow + 4) = make_float4(acc[i][4], acc[i][5], acc[i][6], acc[i][7]);
        float p1 = 0.f, p2 = 0.f;
#pragma unroll
        for (int j = 0; j < 8; j++) {
            p1 = fmaf(acc[i][j], sa[tx * 8 + j], p1);
            p2 = fmaf(acc[i][j], sa[128 + tx * 8 + j], p2);
        }
#pragma unroll
        for (int o = 8; o; o >>= 1) {
            p1 += __shfl_down_sync(0xFFFFFFFFu, p1, o, 16);
            p2 += __shfl_down_sync(0xFFFFFFFFu, p2, o, 16);
        }
        if (tx == 0) { g_s1[m] = p1; g_s2[m] = p2; }
    }
}

// ---- Kernel 2: brute-force rank sort (64 blocks, no barriers in count loop) ----
// rank_j = #{j' : s2_j' < s2_j, tie broken by index}. Exact permutation; any tie
// order is value-equivalent for the threshold predicate and the exp weights.
__global__ void __launch_bounds__(256) rank_kernel() {
    const int b = blockIdx.x >> 3;          // 8 blocks per batch
    const int seg = blockIdx.x & 7;
    const int tid = threadIdx.x;
    __shared__ float vals[2048];
    if (tid < 8) g_flag[blockIdx.x * 8 + tid] = 0;   // 64 blocks x 8 = 512 flags
#pragma unroll
    for (int s = 0; s < 8; s++)
        vals[tid + s * 256] = g_s2[b * N + tid + s * 256];
    __syncthreads();
    const int e = seg * 256 + tid;
    const float v = vals[e];
    int rank = 0;
#pragma unroll 4
    for (int q = 0; q < 512; q++) {
        float4 x = ((const float4*)vals)[q];
        int j0 = q * 4;
        rank += (x.x < v || (x.x == v && j0 + 0 < e));
        rank += (x.y < v || (x.y == v && j0 + 1 < e));
        rank += (x.z < v || (x.z == v && j0 + 2 < e));
        rank += (x.w < v || (x.w == v && j0 + 3 < e));
    }
    g_s2s[b * N + rank] = v;
    g_perm[b * N + rank] = e;
    if (rank == N - 1) g_mx[b] = v;
}

// ---- Kernel 3: fused w=exp + chunk partial + lookback + suffix scan (S and Z) ----
// 512 blocks x 128 thr, 16.6KB smem: all co-resident in wave 1 -> spins are safe.
__global__ void __launch_bounds__(128) fused_scan_kernel() {
    const int b = blockIdx.x >> 6;
    const int g = blockIdx.x & (G2 - 1);
    const int f = threadIdx.x;
    __shared__ float rows[C2][F];
    __shared__ float sw[C2];
    __shared__ int   sp[C2];
    if (f < C2) {
        sw[f] = expf(g_s2s[b * N + g * C2 + f] - g_mx[b]);
        sp[f] = g_perm[b * N + g * C2 + f];
    }
    __syncthreads();
    const float* Whb = g_Wh + (size_t)b * N * 128;
    float accW = 0.f, accM = 0.f;
#pragma unroll 4
    for (int j = 0; j < C2; j++) {
        float x = Whb[(size_t)sp[j] * 128 + f];
        rows[j][f] = x;
        accW = fmaf(sw[j], x, accW);
        accM += x;
    }
    g_pw[b][g][f] = accW;
    g_pm[b][g][f] = accM;
    if (f < 32) {                         // scalar chunk w-sum (one warp)
        float z = sw[f];
#pragma unroll
        for (int o = 16; o; o >>= 1) z += __shfl_down_sync(0xFFFFFFFFu, z, o);
        if (f == 0) g_pz[b][g] = z;
    }
    __syncthreads();
    __threadfence();
    if (f == 0) {
        ((volatile int*)g_flag)[blockIdx.x] = 1;
        for (int gg = g + 1; gg < G2; gg++)
            while (((volatile int*)g_flag)[(b << 6) | gg] == 0) {}
        __threadfence();
    }
    __syncthreads();
    float off = 0.f;
    for (int gg = g + 1; gg < G2; gg++) off += __ldcg(&g_pw[b][gg][f]);
    float acc = off;
    float* Sb = g_S + (size_t)(b * N + g * C2) * 128;
#pragma unroll 4
    for (int j = C2 - 1; j >= 0; j--) {
        acc = fmaf(sw[j], rows[j][f], acc);
        __stcg(&Sb[(size_t)j * 128 + f], acc);
    }
    // scalar Z for this chunk's 32 positions
    if (f < 32) {
        float zoff = 0.f;
        for (int gg = g + 1; gg < G2; gg++) zoff += __ldcg(&g_pz[b][gg]);
        float s = 0.f;
        for (int j2 = 31; j2 >= f; j2--) s += sw[j2];
        g_Z[b * (N + 1) + g * C2 + f] = s + zoff;
    }
    if (g == 0) {
        float m = accM;
        for (int gg = 1; gg < G2; gg++) m += __ldcg(&g_pm[b][gg][f]);
        g_mean[b * 128 + f] = m * (1.f / 2048.f);
    }
}

// ---- Kernel 4: warp per row: 3-round lane-parallel ballot search + elu(S[k]/Z[k]) ----
__global__ void __launch_bounds__(256) out_kernel(float* __restrict__ out) {
    const int warp = threadIdx.x >> 5;
    const int lane = threadIdx.x & 31;
    const int row = blockIdx.x * 8 + warp;          // 0..16383
    const int b = row >> 11;
    const float* ss = g_s2s + b * N;
    const float s1v = g_s1[row];

    bool p1 = (s1v + ss[lane * 64 + 63] > 0.f);
    unsigned m1 = __ballot_sync(0xFFFFFFFFu, p1);
    int lo;
    if (m1 == 0u) {
        lo = N;
    } else {
        int base = (__ffs(m1) - 1) * 64;
        bool p2 = (s1v + ss[base + lane * 2 + 1] > 0.f);
        unsigned m2 = __ballot_sync(0xFFFFFFFFu, p2);
        int cand = base + (__ffs(m2) - 1) * 2;
        lo = (s1v + ss[cand] > 0.f) ? cand : cand + 1;
    }

    float4 v;
    if (lo == N) {
        v = ((const float4*)(g_mean + b * 128))[lane];
    } else {
        float invZ = 1.f / g_Z[b * (N + 1) + lo];
        float4 s = __ldcg(&((const float4*)(g_S + (size_t)(b * N + lo) * 128))[lane]);
        v = make_float4(s.x * invZ, s.y * invZ, s.z * invZ, s.w * invZ);
    }
    v.x = (v.x > 0.f) ? v.x : expm1f(v.x);
    v.y = (v.y > 0.f) ? v.y : expm1f(v.y);
    v.z = (v.z > 0.f) ? v.z : expm1f(v.z);
    v.w = (v.w > 0.f) ? v.w : expm1f(v.w);
    ((float4*)(out + (size_t)row * 128))[lane] = v;
}

// ---------------- launch ----------------
extern "C" void kernel_launch(void* const* d_in, const int* in_sizes, int n_in,
                              void* d_out, int out_size) {
    const float* h = (const float*)d_in[0];   // [8,2048,128]
    const float* W = (const float*)d_in[1];   // [128,128]
    const float* a = (const float*)d_in[2];   // [256,1]
    float* out = (float*)d_out;

    gemm_kernel<<<BN / 128, 256>>>(h, W, a);
    rank_kernel<<<B * 8, 256>>>();
    fused_scan_kernel<<<B * G2, 128>>>();
    out_kernel<<<BN / 8, 256>>>(out);
}

// round 11
// speedup vs baseline: 1.0252x; 1.0252x over previous
#include <cuda_runtime.h>
#include <math.h>

#define B 8
#define N 2048
#define F 128
#define BN (B*N)
#define G2 64          // chunks per batch (scan)
#define C2 32          // rows per chunk (G2*C2 == N)

// ---------------- scratch (device globals) ----------------
__device__ float g_Wh[BN * F];          // 8 MB
__device__ float g_s1[BN];
__device__ float g_s2[BN];
__device__ float g_s2s[BN];             // sorted s2 per batch (ascending)
__device__ int   g_perm[BN];
__device__ float g_w[BN];               // exp(s2s - max), in sorted order
__device__ float g_S[BN * F];           // suffix sums of w_j * Wh[perm[j],:]
__device__ float g_Z[B * (N + 1)];      // scalar suffix sums of w
__device__ float g_mean[B * F];
__device__ float g_pw[B][G2][F];        // chunk partial weighted sums
__device__ float g_pm[B][G2][F];        // chunk partial plain sums (for mean)
__device__ int   g_flag[B * G2];        // chunk-done flags (zeroed by rank_kernel)

// ---- Kernel 1: Wh = h @ W^T. 128x128 tile, 8x8/thread, k-major smem ----
#define SST 132
__global__ void __launch_bounds__(256, 1) gemm_kernel(const float* __restrict__ A,
                                                      const float* __restrict__ W,
                                                      const float* __restrict__ a) {
    __shared__ float AsT[16][SST];
    __shared__ float Bs[16][SST];
    __shared__ float sa[256];
    const int m0 = blockIdx.x * 128;
    const int tid = threadIdx.x;
    sa[tid] = a[tid];

    const int ty = tid >> 4;
    const int tx = tid & 15;

    float acc[8][8];
#pragma unroll
    for (int i = 0; i < 8; i++)
#pragma unroll
        for (int j = 0; j < 8; j++) acc[i][j] = 0.f;

    for (int k0 = 0; k0 < 128; k0 += 16) {
#pragma unroll
        for (int s = 0; s < 2; s++) {
            int q = tid + s * 256;
            int m = q >> 2;
            int kq = (q & 3) * 4;
            float4 av = *(const float4*)(A + (size_t)(m0 + m) * 128 + k0 + kq);
            AsT[kq + 0][m] = av.x; AsT[kq + 1][m] = av.y;
            AsT[kq + 2][m] = av.z; AsT[kq + 3][m] = av.w;
            float4 wv = *(const float4*)(W + (size_t)m * 128 + k0 + kq);
            Bs[kq + 0][m] = wv.x; Bs[kq + 1][m] = wv.y;
            Bs[kq + 2][m] = wv.z; Bs[kq + 3][m] = wv.w;
        }
        __syncthreads();
#pragma unroll
        for (int kk = 0; kk < 16; kk++) {
            float af[8], bf[8];
            *(float4*)&af[0] = *(const float4*)&AsT[kk][ty * 8];
            *(float4*)&af[4] = *(const float4*)&AsT[kk][ty * 8 + 4];
            *(float4*)&bf[0] = *(const float4*)&Bs[kk][tx * 8];
            *(float4*)&bf[4] = *(const float4*)&Bs[kk][tx * 8 + 4];
#pragma unroll
            for (int i = 0; i < 8; i++)
#pragma unroll
                for (int j = 0; j < 8; j++) acc[i][j] = fmaf(af[i], bf[j], acc[i][j]);
        }
        __syncthreads();
    }
#pragma unroll
    for (int i = 0; i < 8; i++) {
        const int m = m0 + ty * 8 + i;
        float* crow = g_Wh + (size_t)m * 128 + tx * 8;
        *(float4*)(crow + 0) = make_float4(acc[i][0], acc[i][1], acc[i][2], acc[i][3]);
        *(float4*)(crow + 4) = make_float4(acc[i][4], acc[i][5], acc[i][6], acc[i][7]);
        float p1 = 0.f, p2 = 0.f;
#pragma unroll
        for (int j = 0; j < 8; j++) {
            p1 = fmaf(acc[i][j], sa[tx * 8 + j], p1);
            p2 = fmaf(acc[i][j], sa[128 + tx * 8 + j], p2);
        }
#pragma unroll
        for (int o = 8; o; o >>= 1) {
            p1 += __shfl_down_sync(0xFFFFFFFFu, p1, o, 16);
            p2 += __shfl_down_sync(0xFFFFFFFFu, p2, o, 16);
        }
        if (tx == 0) { g_s1[m] = p1; g_s2[m] = p2; }
    }
}

// ---- Kernel 2: rank sort v2 (256 blocks; 4 threads/element) + w + Z fused ----
// Each block: whole batch in smem. Computes rank, exp weight, and Z (suffix sum
// of w under the identical tie-break) in one N^2 pass split 4 ways per element.
__global__ void __launch_bounds__(256) rank_kernel() {
    const int b = blockIdx.x >> 5;          // 32 blocks per batch
    const int seg = blockIdx.x & 31;        // 64 elements per block
    const int tid = threadIdx.x;
    const int lane = tid & 31;
    const int wid = tid >> 5;
    __shared__ float vals[2048];
    __shared__ float wv[2048];
    __shared__ float red[16];
    __shared__ int   pr[4][64];
    __shared__ float pzs[4][64];
    if (tid < 2) g_flag[blockIdx.x * 2 + tid] = 0;   // 256 blocks x 2 = 512 flags

    float myv[8];
#pragma unroll
    for (int s = 0; s < 8; s++) {
        myv[s] = g_s2[b * N + tid + s * 256];
        vals[tid + s * 256] = myv[s];
    }
    // block max
    float m = myv[0];
#pragma unroll
    for (int s = 1; s < 8; s++) m = fmaxf(m, myv[s]);
#pragma unroll
    for (int o = 16; o; o >>= 1) m = fmaxf(m, __shfl_xor_sync(0xFFFFFFFFu, m, o));
    if (lane == 0) red[wid] = m;
    __syncthreads();
    if (tid == 0) {
        float mm = red[0];
#pragma unroll
        for (int i = 1; i < 8; i++) mm = fmaxf(mm, red[i]);
        red[0] = mm;
    }
    __syncthreads();
    const float mx = red[0];
    // weights + total
    float zt = 0.f;
#pragma unroll
    for (int s = 0; s < 8; s++) {
        float w = expf(myv[s] - mx);
        wv[tid + s * 256] = w;
        zt += w;
    }
#pragma unroll
    for (int o = 16; o; o >>= 1) zt += __shfl_xor_sync(0xFFFFFFFFu, zt, o);
    if (lane == 0) red[8 + wid] = zt;
    __syncthreads();
    if (tid == 0) {
        float s = 0.f;
#pragma unroll
        for (int i = 0; i < 8; i++) s += red[8 + i];
        red[1] = s;
    }
    __syncthreads();
    const float ztot = red[1];

    // N^2 pass: quarter q covers values [q*512, q*512+512)
    const int quarter = tid >> 6;
    const int el = tid & 63;
    const int e = seg * 64 + el;
    const float v = vals[e];
    const int base4 = quarter * 128;        // float4 index base
    int rank = 0;
    float zp = 0.f;
#pragma unroll 4
    for (int q = 0; q < 128; q++) {
        float4 x = ((const float4*)vals)[base4 + q];
        float4 wq = ((const float4*)wv)[base4 + q];
        int j0 = (base4 + q) * 4;
        bool c0 = (x.x < v) || (x.x == v && j0 + 0 < e);
        bool c1 = (x.y < v) || (x.y == v && j0 + 1 < e);
        bool c2 = (x.z < v) || (x.z == v && j0 + 2 < e);
        bool c3 = (x.w < v) || (x.w == v && j0 + 3 < e);
        rank += c0 + c1 + c2 + c3;
        zp += c0 ? wq.x : 0.f;
        zp += c1 ? wq.y : 0.f;
        zp += c2 ? wq.z : 0.f;
        zp += c3 ? wq.w : 0.f;
    }
    pr[quarter][el] = rank;
    pzs[quarter][el] = zp;
    __syncthreads();
    if (tid < 64) {
        int rk = pr[0][tid] + pr[1][tid] + pr[2][tid] + pr[3][tid];
        float z = pzs[0][tid] + pzs[1][tid] + pzs[2][tid] + pzs[3][tid];
        int ee = seg * 64 + tid;
        g_s2s[b * N + rk] = vals[ee];
        g_perm[b * N + rk] = ee;
        g_w[b * N + rk] = wv[ee];
        g_Z[b * (N + 1) + rk] = ztot - z;   // suffix sum over ranks >= rk
    }
}

// ---- Kernel 3: fused chunk partial + suffix lookback + suffix scan (512 blocks) ----
__global__ void __launch_bounds__(128) fused_scan_kernel() {
    const int b = blockIdx.x >> 6;
    const int g = blockIdx.x & (G2 - 1);
    const int f = threadIdx.x;
    __shared__ float rows[C2][F];
    __shared__ float sw[C2];
    __shared__ int   sp[C2];
    if (f < C2) {
        sw[f] = g_w[b * N + g * C2 + f];
        sp[f] = g_perm[b * N + g * C2 + f];
    }
    __syncthreads();
    const float* Whb = g_Wh + (size_t)b * N * 128;
    float accW = 0.f, accM = 0.f;
#pragma unroll 4
    for (int j = 0; j < C2; j++) {
        float x = Whb[(size_t)sp[j] * 128 + f];
        rows[j][f] = x;
        accW = fmaf(sw[j], x, accW);
        accM += x;
    }
    g_pw[b][g][f] = accW;
    g_pm[b][g][f] = accM;
    __syncthreads();
    __threadfence();
    if (f == 0) {
        ((volatile int*)g_flag)[blockIdx.x] = 1;
        for (int gg = g + 1; gg < G2; gg++)
            while (((volatile int*)g_flag)[(b << 6) | gg] == 0) {}
        __threadfence();
    }
    __syncthreads();
    float off = 0.f;
    for (int gg = g + 1; gg < G2; gg++) off += __ldcg(&g_pw[b][gg][f]);
    float acc = off;
    float* Sb = g_S + (size_t)(b * N + g * C2) * 128;
#pragma unroll 4
    for (int j = C2 - 1; j >= 0; j--) {
        acc = fmaf(sw[j], rows[j][f], acc);
        __stcg(&Sb[(size_t)j * 128 + f], acc);
    }
    if (g == 0) {
        float m = accM;
        for (int gg = 1; gg < G2; gg++) m += __ldcg(&g_pm[b][gg][f]);
        g_mean[b * 128 + f] = m * (1.f / 2048.f);
    }
}

// ---- Kernel 4: warp per row: 3-round lane-parallel ballot search + elu(S[k]/Z[k]) ----
__global__ void __launch_bounds__(256) out_kernel(float* __restrict__ out) {
    const int warp = threadIdx.x >> 5;
    const int lane = threadIdx.x & 31;
    const int row = blockIdx.x * 8 + warp;
    const int b = row >> 11;
    const float* ss = g_s2s + b * N;
    const float s1v = g_s1[row];

    bool p1 = (s1v + ss[lane * 64 + 63] > 0.f);
    unsigned m1 = __ballot_sync(0xFFFFFFFFu, p1);
    int lo;
    if (m1 == 0u) {
        lo = N;
    } else {
        int base = (__ffs(m1) - 1) * 64;
        bool p2 = (s1v + ss[base + lane * 2 + 1] > 0.f);
        unsigned m2 = __ballot_sync(0xFFFFFFFFu, p2);
        int cand = base + (__ffs(m2) - 1) * 2;
        lo = (s1v + ss[cand] > 0.f) ? cand : cand + 1;
    }

    float4 v;
    if (lo == N) {
        v = ((const float4*)(g_mean + b * 128))[lane];
    } else {
        float invZ = 1.f / g_Z[b * (N + 1) + lo];
        float4 s = __ldcg(&((const float4*)(g_S + (size_t)(b * N + lo) * 128))[lane]);
        v = make_float4(s.x * invZ, s.y * invZ, s.z * invZ, s.w * invZ);
    }
    v.x = (v.x > 0.f) ? v.x : expm1f(v.x);
    v.y = (v.y > 0.f) ? v.y : expm1f(v.y);
    v.z = (v.z > 0.f) ? v.z : expm1f(v.z);
    v.w = (v.w > 0.f) ? v.w : expm1f(v.w);
    ((float4*)(out + (size_t)row * 128))[lane] = v;
}

// ---------------- launch ----------------
extern "C" void kernel_launch(void* const* d_in, const int* in_sizes, int n_in,
                              void* d_out, int out_size) {
    const float* h = (const float*)d_in[0];   // [8,2048,128]
    const float* W = (const float*)d_in[1];   // [128,128]
    const float* a = (const float*)d_in[2];   // [256,1]
    float* out = (float*)d_out;

    gemm_kernel<<<BN / 128, 256>>>(h, W, a);
    rank_kernel<<<B * 32, 256>>>();
    fused_scan_kernel<<<B * G2, 128>>>();
    out_kernel<<<BN / 8, 256>>>(out);
}